// round 16
// baseline (speedup 1.0000x reference)
#include <cuda_runtime.h>
#include <cuda_fp16.h>
#include <math.h>
#include <stdint.h>

// ---------------------------------------------------------------------------
// Problem constants
// ---------------------------------------------------------------------------
constexpr int NN  = 20000;
constexpr int NE  = 320000;
constexpr int H   = 256;
constexpr int FE  = 64;
constexpr int FV  = 64;
constexpr int NL  = 4;
constexpr int FL  = 1024;

// ---------------------------------------------------------------------------
// Scratch (device globals; no dynamic allocation allowed)
// ---------------------------------------------------------------------------
__device__ __half g_e16[(size_t)NE * H];    // e_in running master (fp16)
__device__ __half g_t16[(size_t)NE * H];    // per-layer edge temp (fp16)
__device__ float  g_vin[(size_t)NN * H];
__device__ float  g_vp [(size_t)NN * H];
__device__ float  g_vie[(size_t)NN * H];
__device__ float  g_gi [(size_t)NN * 3 * H];
__device__ float  g_gh [(size_t)NN * 3 * H];
__device__ float  g_hbuf[(size_t)NN * H];
__device__ float  g_wcomb[H];
__device__ float  g_bcomb[1];
__device__ float  g_sum[H];
__device__ float  g_sumsq[H];
__device__ float  g_scale[H];
__device__ float  g_shift[H];

// ---------------------------------------------------------------------------
// Utility
// ---------------------------------------------------------------------------
__global__ void zero_k(float* __restrict__ p, int n) {
    int i = blockIdx.x * blockDim.x + threadIdx.x;
    if (i < n) p[i] = 0.0f;
}

__global__ void init_out(float* __restrict__ out, int n) {
    int i = blockIdx.x * blockDim.x + threadIdx.x;
    if (i < n) out[i] = g_bcomb[0];
}

// zero wcomb/bcomb/stat accumulators before the parallel combine
__global__ void zero_small() {
    int h = threadIdx.x;
    g_wcomb[h] = 0.0f;
    g_sum[h] = 0.0f;
    g_sumsq[h] = 0.0f;
    if (h == 0) g_bcomb[0] = 0.0f;
}

// Parallel fold of fin/out tail: 8 blocks x 128 f-rows each.
__global__ void combine_partial(const float* __restrict__ fin_w,
                                const float* __restrict__ fin_b,
                                const float* __restrict__ out_w,
                                const float* __restrict__ out_b) {
    int h = threadIdx.x;
    int b = blockIdx.x;                       // 0..7
    float s = 0.0f;
    for (int f = b * 128; f < (b + 1) * 128; f++)
        s += out_w[f] * fin_w[(size_t)f * H + h];
    atomicAdd(&g_wcomb[h], s);
    if (b == 0) {
        float bb = 0.0f;
#pragma unroll
        for (int j = 0; j < 4; j++) {
            int f = h + j * 256;
            bb += out_w[f] * fin_b[f];
        }
        __shared__ float red[256];
        red[h] = bb;
        __syncthreads();
        for (int o = 128; o > 0; o >>= 1) {
            if (h < o) red[h] += red[h + o];
            __syncthreads();
        }
        if (h == 0) atomicAdd(&g_bcomb[0], out_b[0] + red[0]);
    }
}

// ---------------------------------------------------------------------------
// FP16 tensor-core GEMM: 128x256 block tile, BK=16, 512 threads = 16 warps
// (2x8), warp tile 64x32 (identical per-warp resources to the proven
// 256-thread core -> same 16 warps/SM, but A rows read ONCE per 256 cols).
// ldmatrix.x4.b16 + mma.m16n8k16, fp32 accum.
// AH:   A input already fp16 -> raw uint2 loads.
// FUSE: epilogue t = acc + bias + vp[src]+vp[dst] -> fp16 Y + BN stats.
// ENC:  epilogue writes fp16 Y + atomicAdd dot(row, wcomb) into outv.
// else: fp32 Y.
// Requires: K % 16 == 0, Nc % 256 == 0. M arbitrary.
// ---------------------------------------------------------------------------
#define STRH 24
#define TILE_A_H (128 * STRH)          // 3072 halves
#define TILE_B_H (256 * STRH)          // 6144 halves
#define TILE_A_BYTES (TILE_A_H * 2)
#define TILE_B_BYTES (TILE_B_H * 2)

__device__ __forceinline__ void ldsm_x4(uint32_t& r0, uint32_t& r1,
                                        uint32_t& r2, uint32_t& r3, uint32_t addr) {
    asm volatile("ldmatrix.sync.aligned.m8n8.x4.shared.b16 {%0,%1,%2,%3}, [%4];\n"
                 : "=r"(r0), "=r"(r1), "=r"(r2), "=r"(r3) : "r"(addr));
}
__device__ __forceinline__ uint32_t pack_h2(float a, float b) {
    __half2 h = __floats2half2_rn(a, b);
    return *(uint32_t*)&h;
}

template<bool FUSE, bool AH, bool ENC>
__global__ __launch_bounds__(512)
void gemm_f16(const void* __restrict__ Xv, const float* __restrict__ W,
              const float* __restrict__ bias, void* __restrict__ Yv,
              float* __restrict__ outv,
              int M, int Nc, int K,
              const float* __restrict__ vp, const int* __restrict__ src,
              const int* __restrict__ dst) {
    __shared__ __half As[2][TILE_A_H];
    __shared__ __half Bs[2][TILE_B_H];

    const int tid  = threadIdx.x;
    const int lane = tid & 31;
    const int warp = tid >> 5;              // 0..15
    const int wm   = (warp >> 3) * 64;      // 0,64
    const int wn   = (warp & 7) * 32;       // 0..224
    const int bm   = blockIdx.y * 128;
    const int bn   = blockIdx.x * 256;

    float acc[4][4][4];
#pragma unroll
    for (int i = 0; i < 4; i++)
#pragma unroll
        for (int j = 0; j < 4; j++)
#pragma unroll
            for (int c = 0; c < 4; c++) acc[i][j][c] = 0.0f;

    const int KT = K >> 4;

    const int l_row = tid >> 2;             // 0..127
    const int l_c4  = (tid & 3) << 2;       // 0,4,8,12

    const uint32_t smA = (uint32_t)__cvta_generic_to_shared(&As[0][0]);
    const uint32_t smB = (uint32_t)__cvta_generic_to_shared(&Bs[0][0]);
    const uint32_t a_lane = (wm + (lane & 15)) * (STRH * 2) + (lane >> 4) * 16;
    const uint32_t b_lane = (wn + (lane & 15)) * (STRH * 2) + (lane >> 4) * 16;

    float4 ra, rb0, rb1;
    uint2  ha;
    auto ldg_tile = [&](int kt) {
        int ar = bm + l_row;
        if (AH) {
            const __half* Xh = (const __half*)Xv;
            ha = (ar < M) ? *(const uint2*)(Xh + (size_t)ar * K + kt * 16 + l_c4)
                          : make_uint2(0u, 0u);
        } else {
            const float* Xf = (const float*)Xv;
            ra = (ar < M) ? *(const float4*)(Xf + (size_t)ar * K + kt * 16 + l_c4)
                          : make_float4(0.f, 0.f, 0.f, 0.f);
        }
        rb0 = *(const float4*)(W + (size_t)(bn + l_row) * K + kt * 16 + l_c4);
        rb1 = *(const float4*)(W + (size_t)(bn + 128 + l_row) * K + kt * 16 + l_c4);
    };
    auto sts_tile = [&](int buf) {
        if (AH) {
            *(uint2*)&As[buf][l_row * STRH + l_c4] = ha;
        } else {
            uint2 ta = make_uint2(pack_h2(ra.x, ra.y), pack_h2(ra.z, ra.w));
            *(uint2*)&As[buf][l_row * STRH + l_c4] = ta;
        }
        uint2 tb0 = make_uint2(pack_h2(rb0.x, rb0.y), pack_h2(rb0.z, rb0.w));
        uint2 tb1 = make_uint2(pack_h2(rb1.x, rb1.y), pack_h2(rb1.z, rb1.w));
        *(uint2*)&Bs[buf][l_row * STRH + l_c4] = tb0;
        *(uint2*)&Bs[buf][(l_row + 128) * STRH + l_c4] = tb1;
    };

    ldg_tile(0);
    sts_tile(0);

    for (int kt = 0; kt < KT; kt++) {
        __syncthreads();
        const int buf = kt & 1;
        if (kt + 1 < KT) ldg_tile(kt + 1);

        const uint32_t baseA = smA + buf * TILE_A_BYTES + a_lane;
        const uint32_t baseB = smB + buf * TILE_B_BYTES + b_lane;

        uint32_t a[4][4], bq[2][4];
#pragma unroll
        for (int mf = 0; mf < 4; mf++)
            ldsm_x4(a[mf][0], a[mf][1], a[mf][2], a[mf][3],
                    baseA + mf * 16 * (STRH * 2));
#pragma unroll
        for (int j = 0; j < 2; j++)
            ldsm_x4(bq[j][0], bq[j][1], bq[j][2], bq[j][3],
                    baseB + j * 16 * (STRH * 2));

#pragma unroll
        for (int mf = 0; mf < 4; mf++)
#pragma unroll
            for (int nf = 0; nf < 4; nf++) {
                uint32_t b0 = bq[nf >> 1][(nf & 1)];
                uint32_t b1 = bq[nf >> 1][(nf & 1) + 2];
                asm volatile(
                    "mma.sync.aligned.m16n8k16.row.col.f32.f16.f16.f32 "
                    "{%0,%1,%2,%3},{%4,%5,%6,%7},{%8,%9},{%0,%1,%2,%3};\n"
                    : "+f"(acc[mf][nf][0]), "+f"(acc[mf][nf][1]),
                      "+f"(acc[mf][nf][2]), "+f"(acc[mf][nf][3])
                    : "r"(a[mf][0]), "r"(a[mf][1]), "r"(a[mf][2]), "r"(a[mf][3]),
                      "r"(b0), "r"(b1));
            }
        if (kt + 1 < KT) sts_tile(buf ^ 1);
    }

    float bv[4][2];
#pragma unroll
    for (int nf = 0; nf < 4; nf++) {
        int col = bn + wn + nf * 8 + (lane & 3) * 2;
        bv[nf][0] = bias[col];
        bv[nf][1] = bias[col + 1];
    }

    if (FUSE) {
        // t = acc + bias + vp[src] + vp[dst]  -> fp16 Y + BN stats
        __half* Y = (__half*)Yv;
        float csum[8], csq[8];
#pragma unroll
        for (int i = 0; i < 8; i++) { csum[i] = 0.f; csq[i] = 0.f; }

#pragma unroll
        for (int mf = 0; mf < 4; mf++) {
#pragma unroll
            for (int half = 0; half < 2; half++) {
                int row = bm + wm + mf * 16 + (lane >> 2) + half * 8;
                if (row < M) {
                    int va = src[row], vb = dst[row];
                    const float* pa = vp + (size_t)va * 256;
                    const float* pb = vp + (size_t)vb * 256;
#pragma unroll
                    for (int nf = 0; nf < 4; nf++) {
                        int col = bn + wn + nf * 8 + (lane & 3) * 2;
                        float2 ga = *(const float2*)(pa + col);
                        float2 gb = *(const float2*)(pb + col);
                        float v0 = acc[mf][nf][half * 2 + 0] + bv[nf][0] + ga.x + gb.x;
                        float v1 = acc[mf][nf][half * 2 + 1] + bv[nf][1] + ga.y + gb.y;
                        __half2 hv = __floats2half2_rn(v0, v1);
                        *(__half2*)(Y + (size_t)row * Nc + col) = hv;
                        csum[nf * 2 + 0] += v0;  csq[nf * 2 + 0] += v0 * v0;
                        csum[nf * 2 + 1] += v1;  csq[nf * 2 + 1] += v1 * v1;
                    }
                }
            }
        }
#pragma unroll
        for (int off = 16; off >= 4; off >>= 1) {
#pragma unroll
            for (int i = 0; i < 8; i++) {
                csum[i] += __shfl_xor_sync(0xFFFFFFFFu, csum[i], off);
                csq[i]  += __shfl_xor_sync(0xFFFFFFFFu, csq[i],  off);
            }
        }
        __syncthreads();
        float* ssum = (float*)&As[0][0];   // [256]
        float* ssq  = ssum + 256;          // [256]
        ((float*)&As[0][0])[tid] = 0.f;    // zeroes both (tid 0..511)
        __syncthreads();
        if (lane < 4) {
#pragma unroll
            for (int nf = 0; nf < 4; nf++) {
#pragma unroll
                for (int c = 0; c < 2; c++) {
                    int lcol = wn + nf * 8 + lane * 2 + c;   // 0..255
                    atomicAdd(&ssum[lcol], csum[nf * 2 + c]);
                    atomicAdd(&ssq[lcol],  csq[nf * 2 + c]);
                }
            }
        }
        __syncthreads();
        if (tid < 256) {
            atomicAdd(&g_sum[bn + tid],   ssum[tid]);
            atomicAdd(&g_sumsq[bn + tid], ssq[tid]);
        }
    } else if (ENC) {
        // encoder: write fp16 Y + seed out[row] with dot(row, wcomb)
        __half* Y = (__half*)Yv;
        float part[8];
#pragma unroll
        for (int i = 0; i < 8; i++) part[i] = 0.f;

#pragma unroll
        for (int nf = 0; nf < 4; nf++) {
            int col = bn + wn + nf * 8 + (lane & 3) * 2;
            float w0 = g_wcomb[col], w1 = g_wcomb[col + 1];
#pragma unroll
            for (int mf = 0; mf < 4; mf++) {
                int row = bm + wm + mf * 16 + (lane >> 2);
                if (row < M) {
                    float o0 = acc[mf][nf][0] + bv[nf][0];
                    float o1 = acc[mf][nf][1] + bv[nf][1];
                    *(__half2*)(Y + (size_t)row * Nc + col) = __floats2half2_rn(o0, o1);
                    part[mf * 2 + 0] += o0 * w0 + o1 * w1;
                }
                if (row + 8 < M) {
                    float o0 = acc[mf][nf][2] + bv[nf][0];
                    float o1 = acc[mf][nf][3] + bv[nf][1];
                    *(__half2*)(Y + (size_t)(row + 8) * Nc + col) = __floats2half2_rn(o0, o1);
                    part[mf * 2 + 1] += o0 * w0 + o1 * w1;
                }
            }
        }
#pragma unroll
        for (int off = 1; off <= 2; off <<= 1)
#pragma unroll
            for (int i = 0; i < 8; i++)
                part[i] += __shfl_xor_sync(0xFFFFFFFFu, part[i], off);
        if ((lane & 3) == 0) {
#pragma unroll
            for (int mf = 0; mf < 4; mf++)
#pragma unroll
                for (int half = 0; half < 2; half++) {
                    int row = bm + wm + mf * 16 + (lane >> 2) + half * 8;
                    if (row < M) atomicAdd(&outv[row], part[mf * 2 + half]);
                }
        }
    } else {
        float* Y = (float*)Yv;
#pragma unroll
        for (int nf = 0; nf < 4; nf++) {
            int col = bn + wn + nf * 8 + (lane & 3) * 2;
#pragma unroll
            for (int mf = 0; mf < 4; mf++) {
                int row = bm + wm + mf * 16 + (lane >> 2);
                if (row < M) {
                    *(float2*)(Y + (size_t)row * Nc + col) =
                        make_float2(acc[mf][nf][0] + bv[nf][0],
                                    acc[mf][nf][1] + bv[nf][1]);
                }
                if (row + 8 < M) {
                    *(float2*)(Y + (size_t)(row + 8) * Nc + col) =
                        make_float2(acc[mf][nf][2] + bv[nf][0],
                                    acc[mf][nf][3] + bv[nf][1]);
                }
            }
        }
    }
}

// ---------------------------------------------------------------------------
// Finalize BN; re-zeroes stat accumulators for the next pass.
// ---------------------------------------------------------------------------
__global__ void bn_finalize(const float* __restrict__ g, const float* __restrict__ b,
                            float inv_n) {
    int h = threadIdx.x;
    float mean = g_sum[h] * inv_n;
    float var = g_sumsq[h] * inv_n - mean * mean;
    float sc = g[h] * rsqrtf(var + 1e-5f);
    g_scale[h] = sc;
    g_shift[h] = b[h] - mean * sc;
    g_sum[h] = 0.0f;
    g_sumsq[h] = 0.0f;
}

// ---------------------------------------------------------------------------
// Warp-per-edge scatter: ep = relu(bn(t16)).
//  - out[e] += dot(ep, wcomb)
//  - !LAST: predicated scatter-max into vie (v>0 only); e16 += ep.
// ---------------------------------------------------------------------------
template<bool LAST>
__global__ void scatter_edge(const uint2* __restrict__ t16, uint2* __restrict__ e16,
                             float* __restrict__ vie, float* __restrict__ outv,
                             const int* __restrict__ src, const int* __restrict__ dst,
                             int E) {
    int gw   = (blockIdx.x * blockDim.x + threadIdx.x) >> 5;
    int lane = threadIdx.x & 31;
    if (gw >= E) return;
    size_t base = (size_t)gw * 64;

    int a = 0, b = 0;
    if (!LAST) { a = src[gw]; b = dst[gw]; }

    float part = 0.f;
#pragma unroll
    for (int j = 0; j < 2; j++) {
        int c4 = lane + j * 32;
        int h4 = c4 << 2;
        size_t idx = base + c4;
        uint2 tv = t16[idx];
        float2 f01 = __half22float2(*(__half2*)&tv.x);
        float2 f23 = __half22float2(*(__half2*)&tv.y);
        float vx = fmaxf(fmaf(f01.x, g_scale[h4 + 0], g_shift[h4 + 0]), 0.f);
        float vy = fmaxf(fmaf(f01.y, g_scale[h4 + 1], g_shift[h4 + 1]), 0.f);
        float vz = fmaxf(fmaf(f23.x, g_scale[h4 + 2], g_shift[h4 + 2]), 0.f);
        float vw = fmaxf(fmaf(f23.y, g_scale[h4 + 3], g_shift[h4 + 3]), 0.f);
        part += vx * g_wcomb[h4 + 0] + vy * g_wcomb[h4 + 1]
              + vz * g_wcomb[h4 + 2] + vw * g_wcomb[h4 + 3];
        if (!LAST) {
            int* pa = (int*)&vie[(size_t)a * H + h4];
            int* pb = (int*)&vie[(size_t)b * H + h4];
            if (vx > 0.f) { atomicMax(pa + 0, __float_as_int(vx));
                            atomicMax(pb + 0, __float_as_int(vx)); }
            if (vy > 0.f) { atomicMax(pa + 1, __float_as_int(vy));
                            atomicMax(pb + 1, __float_as_int(vy)); }
            if (vz > 0.f) { atomicMax(pa + 2, __float_as_int(vz));
                            atomicMax(pb + 2, __float_as_int(vz)); }
            if (vw > 0.f) { atomicMax(pa + 3, __float_as_int(vw));
                            atomicMax(pb + 3, __float_as_int(vw)); }
            uint2 ev = e16[idx];
            float2 e01 = __half22float2(*(__half2*)&ev.x);
            float2 e23 = __half22float2(*(__half2*)&ev.y);
            __half2 h01 = __floats2half2_rn(e01.x + vx, e01.y + vy);
            __half2 h23 = __floats2half2_rn(e23.x + vz, e23.y + vw);
            uint2 o;
            o.x = *(uint32_t*)&h01;
            o.y = *(uint32_t*)&h23;
            e16[idx] = o;
        }
    }
#pragma unroll
    for (int off = 16; off > 0; off >>= 1)
        part += __shfl_xor_sync(0xFFFFFFFFu, part, off);
    if (lane == 0) atomicAdd(&outv[gw], part);
}

// ---------------------------------------------------------------------------
// GRU gate math + BN stats on h (fast-math gates; memory-bound anyway).
// ---------------------------------------------------------------------------
__device__ __forceinline__ float fast_sigmoid(float x) {
    return 1.0f / (1.0f + __expf(-x));
}
__device__ __forceinline__ float fast_tanh(float x) {
    return 2.0f / (1.0f + __expf(-2.0f * x)) - 1.0f;
}

__global__ void gru_elem(const float* __restrict__ gi, const float* __restrict__ gh,
                         const float* __restrict__ vin, float* __restrict__ hbuf,
                         int N) {
    size_t total = (size_t)N * H;
    size_t stride = (size_t)gridDim.x * blockDim.x;
    int h = threadIdx.x & (H - 1);
    float s = 0.f, s2 = 0.f;
    bool any = false;
    for (size_t idx = (size_t)blockIdx.x * blockDim.x + threadIdx.x; idx < total;
         idx += stride) {
        int n = (int)(idx >> 8);
        const float* giR = gi + (size_t)n * (3 * H);
        const float* ghR = gh + (size_t)n * (3 * H);
        float ir = giR[h], iz = giR[h + H], ig = giR[h + 2 * H];
        float hr = ghR[h], hz = ghR[h + H], hg = ghR[h + 2 * H];
        float r = fast_sigmoid(ir + hr);
        float z = fast_sigmoid(iz + hz);
        float nn = fast_tanh(ig + r * hg);
        float hv = (1.0f - z) * nn + z * vin[idx];
        hbuf[idx] = hv;
        s += hv;
        s2 += hv * hv;
        any = true;
    }
    if (any) {
        atomicAdd(&g_sum[h], s);
        atomicAdd(&g_sumsq[h], s2);
    }
}

__global__ void v_update(float* __restrict__ vin, const float* __restrict__ hbuf,
                         int total) {
    int stride = gridDim.x * blockDim.x;
    for (int idx = blockIdx.x * blockDim.x + threadIdx.x; idx < total; idx += stride) {
        int h = idx & (H - 1);
        float v = fmaf(hbuf[idx], g_scale[h], g_shift[h]);
        vin[idx] += fmaxf(v, 0.0f);
    }
}

// ---------------------------------------------------------------------------
// Launch — R12 dependency structure; s2 forked BEFORE the combine chain so
// the node encoder overlaps it. All waits follow their records (host order).
// ---------------------------------------------------------------------------
extern "C" void kernel_launch(void* const* d_in, const int* in_sizes, int n_in,
                              void* d_out, int out_size) {
    const float* x         = (const float*)d_in[0];
    const float* edge_attr = (const float*)d_in[1];
    const int*   edge_idx  = (const int*)  d_in[2];
    const float* ew        = (const float*)d_in[3];
    const float* eb        = (const float*)d_in[4];
    const float* vw        = (const float*)d_in[5];
    const float* vb        = (const float*)d_in[6];
    const float* Le_w      = (const float*)d_in[7];
    const float* Le_b      = (const float*)d_in[8];
    const float* Lv_w      = (const float*)d_in[9];
    const float* Lv_b      = (const float*)d_in[10];
    const float* bne_g     = (const float*)d_in[11];
    const float* bne_b     = (const float*)d_in[12];
    const float* bnv_g     = (const float*)d_in[13];
    const float* bnv_b     = (const float*)d_in[14];
    const float* gru_wih   = (const float*)d_in[15];
    const float* gru_whh   = (const float*)d_in[16];
    const float* gru_bih   = (const float*)d_in[17];
    const float* gru_bhh   = (const float*)d_in[18];
    const float* fin_w     = (const float*)d_in[19];
    const float* fin_b     = (const float*)d_in[20];
    const float* out_w     = (const float*)d_in[21];
    const float* out_b     = (const float*)d_in[22];
    float* out = (float*)d_out;

    const int E = in_sizes[1] / FE;
    const int N = in_sizes[0] / FV;
    const int* src = edge_idx;
    const int* dst = edge_idx + E;

    float *p_vin, *p_vp, *p_vie, *p_gi, *p_gh, *p_hbuf;
    __half *p_e16, *p_t16;
    cudaGetSymbolAddress((void**)&p_e16,  g_e16);
    cudaGetSymbolAddress((void**)&p_t16,  g_t16);
    cudaGetSymbolAddress((void**)&p_vin,  g_vin);
    cudaGetSymbolAddress((void**)&p_vp,   g_vp);
    cudaGetSymbolAddress((void**)&p_vie,  g_vie);
    cudaGetSymbolAddress((void**)&p_gi,   g_gi);
    cudaGetSymbolAddress((void**)&p_gh,   g_gh);
    cudaGetSymbolAddress((void**)&p_hbuf, g_hbuf);

    const int nbE = (E + 127) / 128;
    const int nbN = (N + 127) / 128;

    cudaStream_t s2;
    cudaStreamCreateWithFlags(&s2, cudaStreamNonBlocking);
    cudaEvent_t evFork, evVZ[NL], evGH[NL], evVU[NL], evGI[NL];
    cudaEventCreateWithFlags(&evFork, cudaEventDisableTiming);
    for (int k = 0; k < NL; k++) {
        cudaEventCreateWithFlags(&evVZ[k], cudaEventDisableTiming);
        cudaEventCreateWithFlags(&evGH[k], cudaEventDisableTiming);
        cudaEventCreateWithFlags(&evVU[k], cudaEventDisableTiming);
        cudaEventCreateWithFlags(&evGI[k], cudaEventDisableTiming);
    }

    // fork early: node encoder (no wcomb dependency) overlaps the combine
    cudaEventRecord(evFork, 0);
    cudaStreamWaitEvent(s2, evFork, 0);

    // s2: node encoder -> zero vie(0)
    gemm_f16<false, false, false><<<dim3(1, nbN), 512, 0, s2>>>(
        x, vw, vb, p_vin, nullptr, N, H, FV, nullptr, nullptr, nullptr);
    zero_k<<<(N * H + 255) / 256, 256, 0, s2>>>(p_vie, N * H);
    cudaEventRecord(evVZ[0], s2);

    // main: fold fin/out tail (parallel) + out init
    zero_small<<<1, H>>>();
    combine_partial<<<8, H>>>(fin_w, fin_b, out_w, out_b);
    init_out<<<(E + 255) / 256, 256>>>(out, E);

    // main: edge encoder -> e16 + seed out with dot(e_in0, wcomb)
    gemm_f16<false, false, true><<<dim3(1, nbE), 512>>>(
        edge_attr, ew, eb, p_e16, out, E, H, FE, nullptr, nullptr, nullptr);

    cudaStreamWaitEvent(0, evVZ[0], 0);

    for (int k = 0; k < NL; k++) {
        const bool last = (k == NL - 1);

        // s2: gh = vin @ whh^T + bhh (dead on last layer)
        if (!last) {
            if (k > 0) cudaStreamWaitEvent(s2, evVU[k - 1], 0);
            gemm_f16<false, false, false><<<dim3(3, nbN), 512, 0, s2>>>(
                p_vin, gru_whh + (size_t)k * 3 * H * H, gru_bhh + (size_t)k * 3 * H,
                p_gh, nullptr, N, 3 * H, H, nullptr, nullptr, nullptr);
            cudaEventRecord(evGH[k], s2);
        }
        if (k > 0 && !last) {
            cudaStreamWaitEvent(s2, evGI[k - 1], 0);
            zero_k<<<(N * H + 255) / 256, 256, 0, s2>>>(p_vie, N * H);
            cudaEventRecord(evVZ[k], s2);
        }

        // main: vp = v_in @ Lv_w^T + Lv_b
        gemm_f16<false, false, false><<<dim3(1, nbN), 512>>>(
            p_vin, Lv_w + (size_t)k * H * H, Lv_b + k * H, p_vp, nullptr,
            N, H, H, nullptr, nullptr, nullptr);

        // main: t16 = fp16(e16 @ Le_w^T + Le_b + vp[src] + vp[dst]) + BN stats
        gemm_f16<true, true, false><<<dim3(1, nbE), 512>>>(
            p_e16, Le_w + (size_t)k * H * H, Le_b + k * H, p_t16, nullptr,
            E, H, H, p_vp, src, dst);
        bn_finalize<<<1, H>>>(bne_g + k * H, bne_b + k * H, 1.0f / (float)E);

        if (!last) {
            cudaStreamWaitEvent(0, evVZ[k], 0);
            scatter_edge<false><<<(E * 32 + 255) / 256, 256>>>(
                (const uint2*)p_t16, (uint2*)p_e16, p_vie, out, src, dst, E);

            // main: gi = vie @ wih^T + bih
            gemm_f16<false, false, false><<<dim3(3, nbN), 512>>>(
                p_vie, gru_wih + (size_t)k * 3 * H * H, gru_bih + (size_t)k * 3 * H,
                p_gi, nullptr, N, 3 * H, H, nullptr, nullptr, nullptr);
            cudaEventRecord(evGI[k], 0);

            // main: GRU gate math + vin update
            cudaStreamWaitEvent(0, evGH[k], 0);
            gru_elem<<<512, 256>>>(p_gi, p_gh, p_vin, p_hbuf, N);
            bn_finalize<<<1, H>>>(bnv_g + k * H, bnv_b + k * H, 1.0f / (float)N);
            v_update<<<2048, 256>>>(p_vin, p_hbuf, N * H);
            cudaEventRecord(evVU[k], 0);
        } else {
            scatter_edge<true><<<(E * 32 + 255) / 256, 256>>>(
                (const uint2*)p_t16, nullptr, nullptr, out, src, dst, E);
        }
    }
}

// round 17
// speedup vs baseline: 1.0334x; 1.0334x over previous
#include <cuda_runtime.h>
#include <cuda_fp16.h>
#include <math.h>
#include <stdint.h>

// ---------------------------------------------------------------------------
// Problem constants
// ---------------------------------------------------------------------------
constexpr int NN  = 20000;
constexpr int NE  = 320000;
constexpr int H   = 256;
constexpr int FE  = 64;
constexpr int FV  = 64;
constexpr int NL  = 4;
constexpr int FL  = 1024;

// ---------------------------------------------------------------------------
// Scratch (device globals; no dynamic allocation allowed)
// ---------------------------------------------------------------------------
__device__ __half g_e16[(size_t)NE * H];    // e_in running master (fp16)
__device__ __half g_t16[(size_t)NE * H];    // per-layer edge temp (fp16)
__device__ float  g_vin[(size_t)NN * H];
__device__ float  g_vp [(size_t)NN * H];
__device__ float  g_vie[(size_t)NN * H];
__device__ float  g_gi [(size_t)NN * 3 * H];
__device__ float  g_gh [(size_t)NN * 3 * H];
__device__ float  g_hbuf[(size_t)NN * H];
__device__ float  g_wcomb[H];
__device__ float  g_bcomb[1];
__device__ float  g_sum[H];
__device__ float  g_sumsq[H];
__device__ float  g_scale[H];
__device__ float  g_shift[H];

// ---------------------------------------------------------------------------
// Utility
// ---------------------------------------------------------------------------
__global__ void zero_k(float* __restrict__ p, int n) {
    int i = blockIdx.x * blockDim.x + threadIdx.x;
    if (i < n) p[i] = 0.0f;
}

__global__ void init_out(float* __restrict__ out, int n) {
    int i = blockIdx.x * blockDim.x + threadIdx.x;
    if (i < n) out[i] = g_bcomb[0];
}

// zero wcomb/bcomb/stat accumulators before the parallel combine
__global__ void zero_small() {
    int h = threadIdx.x;
    g_wcomb[h] = 0.0f;
    g_sum[h] = 0.0f;
    g_sumsq[h] = 0.0f;
    if (h == 0) g_bcomb[0] = 0.0f;
}

// Parallel fold of fin/out tail: 8 blocks x 128 f-rows each.
__global__ void combine_partial(const float* __restrict__ fin_w,
                                const float* __restrict__ fin_b,
                                const float* __restrict__ out_w,
                                const float* __restrict__ out_b) {
    int h = threadIdx.x;
    int b = blockIdx.x;                       // 0..7
    float s = 0.0f;
    for (int f = b * 128; f < (b + 1) * 128; f++)
        s += out_w[f] * fin_w[(size_t)f * H + h];
    atomicAdd(&g_wcomb[h], s);
    if (b == 0) {
        float bb = 0.0f;
#pragma unroll
        for (int j = 0; j < 4; j++) {
            int f = h + j * 256;
            bb += out_w[f] * fin_b[f];
        }
        __shared__ float red[256];
        red[h] = bb;
        __syncthreads();
        for (int o = 128; o > 0; o >>= 1) {
            if (h < o) red[h] += red[h + o];
            __syncthreads();
        }
        if (h == 0) atomicAdd(&g_bcomb[0], out_b[0] + red[0]);
    }
}

// ---------------------------------------------------------------------------
// FP16 tensor-core GEMM (exact R12 core): 128x128 tile, BK=16, 256 threads,
// 8 warps (2x4), warp tile 64x32, ldmatrix.x4.b16 + mma.m16n8k16, fp32 accum.
// AH:   A input is already fp16 (g_e16) -> raw uint2 loads, no convert.
// FUSE: epilogue t = acc + bias + vp[src]+vp[dst] -> fp16 Y + BN stats.
// ENC:  epilogue writes fp16 Y (e16) and atomicAdds dot(row, wcomb) to outv.
// else: fp32 Y.
// Requires: K % 16 == 0, Nc % 128 == 0. M arbitrary.
// ---------------------------------------------------------------------------
#define STRH 24
#define TILE_HALVES (128 * STRH)
#define TILE_BYTES_H (TILE_HALVES * 2)

__device__ __forceinline__ void ldsm_x4(uint32_t& r0, uint32_t& r1,
                                        uint32_t& r2, uint32_t& r3, uint32_t addr) {
    asm volatile("ldmatrix.sync.aligned.m8n8.x4.shared.b16 {%0,%1,%2,%3}, [%4];\n"
                 : "=r"(r0), "=r"(r1), "=r"(r2), "=r"(r3) : "r"(addr));
}
__device__ __forceinline__ uint32_t pack_h2(float a, float b) {
    __half2 h = __floats2half2_rn(a, b);
    return *(uint32_t*)&h;
}

template<bool FUSE, bool AH, bool ENC>
__global__ __launch_bounds__(256)
void gemm_f16(const void* __restrict__ Xv, const float* __restrict__ W,
              const float* __restrict__ bias, void* __restrict__ Yv,
              float* __restrict__ outv,
              int M, int Nc, int K,
              const float* __restrict__ vp, const int* __restrict__ src,
              const int* __restrict__ dst) {
    __shared__ __half As[2][TILE_HALVES];
    __shared__ __half Bs[2][TILE_HALVES];

    const int tid  = threadIdx.x;
    const int lane = tid & 31;
    const int warp = tid >> 5;
    const int wm   = (warp >> 2) * 64;
    const int wn   = (warp & 3) * 32;
    const int bm   = blockIdx.y * 128;
    const int bn   = blockIdx.x * 128;

    float acc[4][4][4];
#pragma unroll
    for (int i = 0; i < 4; i++)
#pragma unroll
        for (int j = 0; j < 4; j++)
#pragma unroll
            for (int c = 0; c < 4; c++) acc[i][j][c] = 0.0f;

    const int KT = K >> 4;

    const int l_row0 = tid >> 2;
    const int l_row1 = (tid + 256) >> 2;
    const int l_c4   = (tid & 3) << 2;

    const uint32_t smA = (uint32_t)__cvta_generic_to_shared(&As[0][0]);
    const uint32_t smB = (uint32_t)__cvta_generic_to_shared(&Bs[0][0]);
    const uint32_t a_lane = (wm + (lane & 15)) * (STRH * 2) + (lane >> 4) * 16;
    const uint32_t b_lane = (wn + (lane & 15)) * (STRH * 2) + (lane >> 4) * 16;

    float4 ra0, ra1, rb0, rb1;
    uint2  ha0, ha1;
    auto ldg_tile = [&](int kt) {
        int ar0 = bm + l_row0, ar1 = bm + l_row1;
        if (AH) {
            const __half* Xh = (const __half*)Xv;
            const uint2 z2 = make_uint2(0u, 0u);
            ha0 = (ar0 < M) ? *(const uint2*)(Xh + (size_t)ar0 * K + kt * 16 + l_c4) : z2;
            ha1 = (ar1 < M) ? *(const uint2*)(Xh + (size_t)ar1 * K + kt * 16 + l_c4) : z2;
        } else {
            const float* Xf = (const float*)Xv;
            const float4 z = make_float4(0.f, 0.f, 0.f, 0.f);
            ra0 = (ar0 < M) ? *(const float4*)(Xf + (size_t)ar0 * K + kt * 16 + l_c4) : z;
            ra1 = (ar1 < M) ? *(const float4*)(Xf + (size_t)ar1 * K + kt * 16 + l_c4) : z;
        }
        rb0 = *(const float4*)(W + (size_t)(bn + l_row0) * K + kt * 16 + l_c4);
        rb1 = *(const float4*)(W + (size_t)(bn + l_row1) * K + kt * 16 + l_c4);
    };
    auto sts_tile = [&](int buf) {
        if (AH) {
            *(uint2*)&As[buf][l_row0 * STRH + l_c4] = ha0;
            *(uint2*)&As[buf][l_row1 * STRH + l_c4] = ha1;
        } else {
            uint2 ta0 = make_uint2(pack_h2(ra0.x, ra0.y), pack_h2(ra0.z, ra0.w));
            uint2 ta1 = make_uint2(pack_h2(ra1.x, ra1.y), pack_h2(ra1.z, ra1.w));
            *(uint2*)&As[buf][l_row0 * STRH + l_c4] = ta0;
            *(uint2*)&As[buf][l_row1 * STRH + l_c4] = ta1;
        }
        uint2 tb0 = make_uint2(pack_h2(rb0.x, rb0.y), pack_h2(rb0.z, rb0.w));
        uint2 tb1 = make_uint2(pack_h2(rb1.x, rb1.y), pack_h2(rb1.z, rb1.w));
        *(uint2*)&Bs[buf][l_row0 * STRH + l_c4] = tb0;
        *(uint2*)&Bs[buf][l_row1 * STRH + l_c4] = tb1;
    };

    ldg_tile(0);
    sts_tile(0);

    for (int kt = 0; kt < KT; kt++) {
        __syncthreads();
        const int buf = kt & 1;
        if (kt + 1 < KT) ldg_tile(kt + 1);

        const uint32_t baseA = smA + buf * TILE_BYTES_H + a_lane;
        const uint32_t baseB = smB + buf * TILE_BYTES_H + b_lane;

        uint32_t a[4][4], bq[2][4];
#pragma unroll
        for (int mf = 0; mf < 4; mf++)
            ldsm_x4(a[mf][0], a[mf][1], a[mf][2], a[mf][3],
                    baseA + mf * 16 * (STRH * 2));
#pragma unroll
        for (int j = 0; j < 2; j++)
            ldsm_x4(bq[j][0], bq[j][1], bq[j][2], bq[j][3],
                    baseB + j * 16 * (STRH * 2));

#pragma unroll
        for (int mf = 0; mf < 4; mf++)
#pragma unroll
            for (int nf = 0; nf < 4; nf++) {
                uint32_t b0 = bq[nf >> 1][(nf & 1)];
                uint32_t b1 = bq[nf >> 1][(nf & 1) + 2];
                asm volatile(
                    "mma.sync.aligned.m16n8k16.row.col.f32.f16.f16.f32 "
                    "{%0,%1,%2,%3},{%4,%5,%6,%7},{%8,%9},{%0,%1,%2,%3};\n"
                    : "+f"(acc[mf][nf][0]), "+f"(acc[mf][nf][1]),
                      "+f"(acc[mf][nf][2]), "+f"(acc[mf][nf][3])
                    : "r"(a[mf][0]), "r"(a[mf][1]), "r"(a[mf][2]), "r"(a[mf][3]),
                      "r"(b0), "r"(b1));
            }
        if (kt + 1 < KT) sts_tile(buf ^ 1);
    }

    float bv[4][2];
#pragma unroll
    for (int nf = 0; nf < 4; nf++) {
        int col = bn + wn + nf * 8 + (lane & 3) * 2;
        bv[nf][0] = bias[col];
        bv[nf][1] = bias[col + 1];
    }

    if (FUSE) {
        // t = acc + bias + vp[src] + vp[dst]  -> fp16 Y + BN stats
        __half* Y = (__half*)Yv;
        float csum[8], csq[8];
#pragma unroll
        for (int i = 0; i < 8; i++) { csum[i] = 0.f; csq[i] = 0.f; }

#pragma unroll
        for (int mf = 0; mf < 4; mf++) {
#pragma unroll
            for (int half = 0; half < 2; half++) {
                int row = bm + wm + mf * 16 + (lane >> 2) + half * 8;
                if (row < M) {
                    int va = src[row], vb = dst[row];
                    const float* pa = vp + (size_t)va * 256;
                    const float* pb = vp + (size_t)vb * 256;
#pragma unroll
                    for (int nf = 0; nf < 4; nf++) {
                        int col = bn + wn + nf * 8 + (lane & 3) * 2;
                        float2 ga = *(const float2*)(pa + col);
                        float2 gb = *(const float2*)(pb + col);
                        float v0 = acc[mf][nf][half * 2 + 0] + bv[nf][0] + ga.x + gb.x;
                        float v1 = acc[mf][nf][half * 2 + 1] + bv[nf][1] + ga.y + gb.y;
                        __half2 hv = __floats2half2_rn(v0, v1);
                        *(__half2*)(Y + (size_t)row * Nc + col) = hv;
                        csum[nf * 2 + 0] += v0;  csq[nf * 2 + 0] += v0 * v0;
                        csum[nf * 2 + 1] += v1;  csq[nf * 2 + 1] += v1 * v1;
                    }
                }
            }
        }
#pragma unroll
        for (int off = 16; off >= 4; off >>= 1) {
#pragma unroll
            for (int i = 0; i < 8; i++) {
                csum[i] += __shfl_xor_sync(0xFFFFFFFFu, csum[i], off);
                csq[i]  += __shfl_xor_sync(0xFFFFFFFFu, csq[i],  off);
            }
        }
        __syncthreads();
        float* ssum = (float*)&As[0][0];
        float* ssq  = ssum + 128;
        if (tid < 128) { ssum[tid] = 0.f; ssq[tid] = 0.f; }
        __syncthreads();
        if (lane < 4) {
#pragma unroll
            for (int nf = 0; nf < 4; nf++) {
#pragma unroll
                for (int c = 0; c < 2; c++) {
                    int lcol = wn + nf * 8 + lane * 2 + c;
                    atomicAdd(&ssum[lcol], csum[nf * 2 + c]);
                    atomicAdd(&ssq[lcol],  csq[nf * 2 + c]);
                }
            }
        }
        __syncthreads();
        if (tid < 128) {
            atomicAdd(&g_sum[bn + tid],   ssum[tid]);
            atomicAdd(&g_sumsq[bn + tid], ssq[tid]);
        }
    } else if (ENC) {
        // encoder: write fp16 e16 + seed out[row] with dot(row, wcomb)
        __half* Y = (__half*)Yv;
        float part[8];
#pragma unroll
        for (int i = 0; i < 8; i++) part[i] = 0.f;

#pragma unroll
        for (int nf = 0; nf < 4; nf++) {
            int col = bn + wn + nf * 8 + (lane & 3) * 2;
            float w0 = g_wcomb[col], w1 = g_wcomb[col + 1];
#pragma unroll
            for (int mf = 0; mf < 4; mf++) {
                int row = bm + wm + mf * 16 + (lane >> 2);
                if (row < M) {
                    float o0 = acc[mf][nf][0] + bv[nf][0];
                    float o1 = acc[mf][nf][1] + bv[nf][1];
                    *(__half2*)(Y + (size_t)row * Nc + col) = __floats2half2_rn(o0, o1);
                    part[mf * 2 + 0] += o0 * w0 + o1 * w1;
                }
                if (row + 8 < M) {
                    float o0 = acc[mf][nf][2] + bv[nf][0];
                    float o1 = acc[mf][nf][3] + bv[nf][1];
                    *(__half2*)(Y + (size_t)(row + 8) * Nc + col) = __floats2half2_rn(o0, o1);
                    part[mf * 2 + 1] += o0 * w0 + o1 * w1;
                }
            }
        }
#pragma unroll
        for (int off = 1; off <= 2; off <<= 1)
#pragma unroll
            for (int i = 0; i < 8; i++)
                part[i] += __shfl_xor_sync(0xFFFFFFFFu, part[i], off);
        if ((lane & 3) == 0) {
#pragma unroll
            for (int mf = 0; mf < 4; mf++)
#pragma unroll
                for (int half = 0; half < 2; half++) {
                    int row = bm + wm + mf * 16 + (lane >> 2) + half * 8;
                    if (row < M) atomicAdd(&outv[row], part[mf * 2 + half]);
                }
        }
    } else {
        float* Y = (float*)Yv;
#pragma unroll
        for (int nf = 0; nf < 4; nf++) {
            int col = bn + wn + nf * 8 + (lane & 3) * 2;
#pragma unroll
            for (int mf = 0; mf < 4; mf++) {
                int row = bm + wm + mf * 16 + (lane >> 2);
                if (row < M) {
                    *(float2*)(Y + (size_t)row * Nc + col) =
                        make_float2(acc[mf][nf][0] + bv[nf][0],
                                    acc[mf][nf][1] + bv[nf][1]);
                }
                if (row + 8 < M) {
                    *(float2*)(Y + (size_t)(row + 8) * Nc + col) =
                        make_float2(acc[mf][nf][2] + bv[nf][0],
                                    acc[mf][nf][3] + bv[nf][1]);
                }
            }
        }
    }
}

// ---------------------------------------------------------------------------
// Finalize BN; re-zeroes stat accumulators for the next pass.
// ---------------------------------------------------------------------------
__global__ void bn_finalize(const float* __restrict__ g, const float* __restrict__ b,
                            float inv_n) {
    int h = threadIdx.x;
    float mean = g_sum[h] * inv_n;
    float var = g_sumsq[h] * inv_n - mean * mean;
    float sc = g[h] * rsqrtf(var + 1e-5f);
    g_scale[h] = sc;
    g_shift[h] = b[h] - mean * sc;
    g_sum[h] = 0.0f;
    g_sumsq[h] = 0.0f;
}

// ---------------------------------------------------------------------------
// Warp-per-edge scatter: ep = relu(bn(t16)).
//  - out[e] += dot(ep, wcomb)          (fp32, one atomicAdd per edge)
//  - !LAST: predicated scatter-max into vie (v>0 only; bitwise-identical,
//           ~50% fewer atomics); e16 += ep (fp16 master RMW).
// ---------------------------------------------------------------------------
template<bool LAST>
__global__ void scatter_edge(const uint2* __restrict__ t16, uint2* __restrict__ e16,
                             float* __restrict__ vie, float* __restrict__ outv,
                             const int* __restrict__ src, const int* __restrict__ dst,
                             int E) {
    int gw   = (blockIdx.x * blockDim.x + threadIdx.x) >> 5;
    int lane = threadIdx.x & 31;
    if (gw >= E) return;
    size_t base = (size_t)gw * 64;

    int a = 0, b = 0;
    if (!LAST) { a = src[gw]; b = dst[gw]; }

    float part = 0.f;
#pragma unroll
    for (int j = 0; j < 2; j++) {
        int c4 = lane + j * 32;
        int h4 = c4 << 2;
        size_t idx = base + c4;
        uint2 tv = t16[idx];
        float2 f01 = __half22float2(*(__half2*)&tv.x);
        float2 f23 = __half22float2(*(__half2*)&tv.y);
        float vx = fmaxf(fmaf(f01.x, g_scale[h4 + 0], g_shift[h4 + 0]), 0.f);
        float vy = fmaxf(fmaf(f01.y, g_scale[h4 + 1], g_shift[h4 + 1]), 0.f);
        float vz = fmaxf(fmaf(f23.x, g_scale[h4 + 2], g_shift[h4 + 2]), 0.f);
        float vw = fmaxf(fmaf(f23.y, g_scale[h4 + 3], g_shift[h4 + 3]), 0.f);
        part += vx * g_wcomb[h4 + 0] + vy * g_wcomb[h4 + 1]
              + vz * g_wcomb[h4 + 2] + vw * g_wcomb[h4 + 3];
        if (!LAST) {
            int* pa = (int*)&vie[(size_t)a * H + h4];
            int* pb = (int*)&vie[(size_t)b * H + h4];
            if (vx > 0.f) { atomicMax(pa + 0, __float_as_int(vx));
                            atomicMax(pb + 0, __float_as_int(vx)); }
            if (vy > 0.f) { atomicMax(pa + 1, __float_as_int(vy));
                            atomicMax(pb + 1, __float_as_int(vy)); }
            if (vz > 0.f) { atomicMax(pa + 2, __float_as_int(vz));
                            atomicMax(pb + 2, __float_as_int(vz)); }
            if (vw > 0.f) { atomicMax(pa + 3, __float_as_int(vw));
                            atomicMax(pb + 3, __float_as_int(vw)); }
            uint2 ev = e16[idx];
            float2 e01 = __half22float2(*(__half2*)&ev.x);
            float2 e23 = __half22float2(*(__half2*)&ev.y);
            __half2 h01 = __floats2half2_rn(e01.x + vx, e01.y + vy);
            __half2 h23 = __floats2half2_rn(e23.x + vz, e23.y + vw);
            uint2 o;
            o.x = *(uint32_t*)&h01;
            o.y = *(uint32_t*)&h23;
            e16[idx] = o;
        }
    }
#pragma unroll
    for (int off = 16; off > 0; off >>= 1)
        part += __shfl_xor_sync(0xFFFFFFFFu, part, off);
    if (lane == 0) atomicAdd(&outv[gw], part);
}

// ---------------------------------------------------------------------------
// GRU gate math + BN stats on h (fast-math gates; memory-bound anyway).
// ---------------------------------------------------------------------------
__device__ __forceinline__ float fast_sigmoid(float x) {
    return 1.0f / (1.0f + __expf(-x));
}
__device__ __forceinline__ float fast_tanh(float x) {
    return 2.0f / (1.0f + __expf(-2.0f * x)) - 1.0f;
}

__global__ void gru_elem(const float* __restrict__ gi, const float* __restrict__ gh,
                         const float* __restrict__ vin, float* __restrict__ hbuf,
                         int N) {
    size_t total = (size_t)N * H;
    size_t stride = (size_t)gridDim.x * blockDim.x;
    int h = threadIdx.x & (H - 1);
    float s = 0.f, s2 = 0.f;
    bool any = false;
    for (size_t idx = (size_t)blockIdx.x * blockDim.x + threadIdx.x; idx < total;
         idx += stride) {
        int n = (int)(idx >> 8);
        const float* giR = gi + (size_t)n * (3 * H);
        const float* ghR = gh + (size_t)n * (3 * H);
        float ir = giR[h], iz = giR[h + H], ig = giR[h + 2 * H];
        float hr = ghR[h], hz = ghR[h + H], hg = ghR[h + 2 * H];
        float r = fast_sigmoid(ir + hr);
        float z = fast_sigmoid(iz + hz);
        float nn = fast_tanh(ig + r * hg);
        float hv = (1.0f - z) * nn + z * vin[idx];
        hbuf[idx] = hv;
        s += hv;
        s2 += hv * hv;
        any = true;
    }
    if (any) {
        atomicAdd(&g_sum[h], s);
        atomicAdd(&g_sumsq[h], s2);
    }
}

__global__ void v_update(float* __restrict__ vin, const float* __restrict__ hbuf,
                         int total) {
    int stride = gridDim.x * blockDim.x;
    for (int idx = blockIdx.x * blockDim.x + threadIdx.x; idx < total; idx += stride) {
        int h = idx & (H - 1);
        float v = fmaf(hbuf[idx], g_scale[h], g_shift[h]);
        vin[idx] += fmaxf(v, 0.0f);
    }
}

// ---------------------------------------------------------------------------
// Launch — R12 dependency structure + head trims: s2 forked before the
// combine chain (node encoder overlaps it); combine parallelized.
// All waits follow their records in host order.
// ---------------------------------------------------------------------------
extern "C" void kernel_launch(void* const* d_in, const int* in_sizes, int n_in,
                              void* d_out, int out_size) {
    const float* x         = (const float*)d_in[0];
    const float* edge_attr = (const float*)d_in[1];
    const int*   edge_idx  = (const int*)  d_in[2];
    const float* ew        = (const float*)d_in[3];
    const float* eb        = (const float*)d_in[4];
    const float* vw        = (const float*)d_in[5];
    const float* vb        = (const float*)d_in[6];
    const float* Le_w      = (const float*)d_in[7];
    const float* Le_b      = (const float*)d_in[8];
    const float* Lv_w      = (const float*)d_in[9];
    const float* Lv_b      = (const float*)d_in[10];
    const float* bne_g     = (const float*)d_in[11];
    const float* bne_b     = (const float*)d_in[12];
    const float* bnv_g     = (const float*)d_in[13];
    const float* bnv_b     = (const float*)d_in[14];
    const float* gru_wih   = (const float*)d_in[15];
    const float* gru_whh   = (const float*)d_in[16];
    const float* gru_bih   = (const float*)d_in[17];
    const float* gru_bhh   = (const float*)d_in[18];
    const float* fin_w     = (const float*)d_in[19];
    const float* fin_b     = (const float*)d_in[20];
    const float* out_w     = (const float*)d_in[21];
    const float* out_b     = (const float*)d_in[22];
    float* out = (float*)d_out;

    const int E = in_sizes[1] / FE;
    const int N = in_sizes[0] / FV;
    const int* src = edge_idx;
    const int* dst = edge_idx + E;

    float *p_vin, *p_vp, *p_vie, *p_gi, *p_gh, *p_hbuf;
    __half *p_e16, *p_t16;
    cudaGetSymbolAddress((void**)&p_e16,  g_e16);
    cudaGetSymbolAddress((void**)&p_t16,  g_t16);
    cudaGetSymbolAddress((void**)&p_vin,  g_vin);
    cudaGetSymbolAddress((void**)&p_vp,   g_vp);
    cudaGetSymbolAddress((void**)&p_vie,  g_vie);
    cudaGetSymbolAddress((void**)&p_gi,   g_gi);
    cudaGetSymbolAddress((void**)&p_gh,   g_gh);
    cudaGetSymbolAddress((void**)&p_hbuf, g_hbuf);

    const int nbE = (E + 127) / 128;
    const int nbN = (N + 127) / 128;

    cudaStream_t s2;
    cudaStreamCreateWithFlags(&s2, cudaStreamNonBlocking);
    cudaEvent_t evFork, evVZ[NL], evGH[NL], evVU[NL], evGI[NL];
    cudaEventCreateWithFlags(&evFork, cudaEventDisableTiming);
    for (int k = 0; k < NL; k++) {
        cudaEventCreateWithFlags(&evVZ[k], cudaEventDisableTiming);
        cudaEventCreateWithFlags(&evGH[k], cudaEventDisableTiming);
        cudaEventCreateWithFlags(&evVU[k], cudaEventDisableTiming);
        cudaEventCreateWithFlags(&evGI[k], cudaEventDisableTiming);
    }

    // fork early: node encoder (no wcomb dependency) overlaps the combine
    cudaEventRecord(evFork, 0);
    cudaStreamWaitEvent(s2, evFork, 0);

    // s2: node encoder -> zero vie(0)
    gemm_f16<false, false, false><<<dim3(H / 128, nbN), 256, 0, s2>>>(
        x, vw, vb, p_vin, nullptr, N, H, FV, nullptr, nullptr, nullptr);
    zero_k<<<(N * H + 255) / 256, 256, 0, s2>>>(p_vie, N * H);
    cudaEventRecord(evVZ[0], s2);

    // main: fold fin/out tail (parallel) + out init
    zero_small<<<1, H>>>();
    combine_partial<<<8, H>>>(fin_w, fin_b, out_w, out_b);
    init_out<<<(E + 255) / 256, 256>>>(out, E);

    // main: edge encoder -> e16 + seed out with dot(e_in0, wcomb)
    gemm_f16<false, false, true><<<dim3(H / 128, nbE), 256>>>(
        edge_attr, ew, eb, p_e16, out, E, H, FE, nullptr, nullptr, nullptr);

    cudaStreamWaitEvent(0, evVZ[0], 0);

    for (int k = 0; k < NL; k++) {
        const bool last = (k == NL - 1);

        // s2: gh = vin @ whh^T + bhh (dead on last layer)
        if (!last) {
            if (k > 0) cudaStreamWaitEvent(s2, evVU[k - 1], 0);
            gemm_f16<false, false, false><<<dim3(3 * H / 128, nbN), 256, 0, s2>>>(
                p_vin, gru_whh + (size_t)k * 3 * H * H, gru_bhh + (size_t)k * 3 * H,
                p_gh, nullptr, N, 3 * H, H, nullptr, nullptr, nullptr);
            cudaEventRecord(evGH[k], s2);
        }
        if (k > 0 && !last) {
            cudaStreamWaitEvent(s2, evGI[k - 1], 0);
            zero_k<<<(N * H + 255) / 256, 256, 0, s2>>>(p_vie, N * H);
            cudaEventRecord(evVZ[k], s2);
        }

        // main: vp = v_in @ Lv_w^T + Lv_b
        gemm_f16<false, false, false><<<dim3(H / 128, nbN), 256>>>(
            p_vin, Lv_w + (size_t)k * H * H, Lv_b + k * H, p_vp, nullptr,
            N, H, H, nullptr, nullptr, nullptr);

        // main: t16 = fp16(e16 @ Le_w^T + Le_b + vp[src] + vp[dst]) + BN stats
        gemm_f16<true, true, false><<<dim3(H / 128, nbE), 256>>>(
            p_e16, Le_w + (size_t)k * H * H, Le_b + k * H, p_t16, nullptr,
            E, H, H, p_vp, src, dst);
        bn_finalize<<<1, H>>>(bne_g + k * H, bne_b + k * H, 1.0f / (float)E);

        if (!last) {
            cudaStreamWaitEvent(0, evVZ[k], 0);
            scatter_edge<false><<<(E * 32 + 255) / 256, 256>>>(
                (const uint2*)p_t16, (uint2*)p_e16, p_vie, out, src, dst, E);

            // main: gi = vie @ wih^T + bih
            gemm_f16<false, false, false><<<dim3(3 * H / 128, nbN), 256>>>(
                p_vie, gru_wih + (size_t)k * 3 * H * H, gru_bih + (size_t)k * 3 * H,
                p_gi, nullptr, N, 3 * H, H, nullptr, nullptr, nullptr);
            cudaEventRecord(evGI[k], 0);

            // main: GRU gate math + vin update
            cudaStreamWaitEvent(0, evGH[k], 0);
            gru_elem<<<512, 256>>>(p_gi, p_gh, p_vin, p_hbuf, N);
            bn_finalize<<<1, H>>>(bnv_g + k * H, bnv_b + k * H, 1.0f / (float)N);
            v_update<<<2048, 256>>>(p_vin, p_hbuf, N * H);
            cudaEventRecord(evVU[k], 0);
        } else {
            scatter_edge<true><<<(E * 32 + 255) / 256, 256>>>(
                (const uint2*)p_t16, nullptr, nullptr, out, src, dst, E);
        }
    }
}